// round 9
// baseline (speedup 1.0000x reference)
#include <cuda_runtime.h>

// Embedding_6940667150787: out[i][d] = wordlist[idx[i]][d] + PE(i, d)
// PE(i, 2j)   = sin(i / 10000^(j/256))   j in [0, 255)
// PE(i, 2j+1) = cos(i / 10000^(j/256))
// cols 510, 511: PE = 0 (emb only)
//
// SMEM-staged variant: block = (512 rows x 1 column-strip of 128 floats).
// Wordlist strip (198 x 512B = 99KB) + idx chunk staged in SMEM once,
// then all rows served from SMEM -> L2 read traffic cut ~2.6x.

#define NROWS 131072
#define DEPTH 512
#define NPAIR 255
#define VOCAB 198
#define STRIPS 4
#define STRIP_F4 32                       // float4 per strip = 128 floats
#define RPB 512                           // rows per block
#define NTHREADS 512                      // 16 warps: 16 rows per iteration
#define ROWGROUPS (NROWS / RPB)           // 256
#define SMEM_WL_F4 (VOCAB * STRIP_F4)     // 6336 float4 = 101376 B
#define SMEM_BYTES (SMEM_WL_F4 * 16 + RPB * 4)   // + 2048 idx = 103424 B

// ---------------------------------------------------------------------------
// Compile-time double-precision exp (range reduction + 25-term Taylor),
// ~1 ulp of double -> exact after fp32 cast. Tables baked into the cubin.
// ---------------------------------------------------------------------------
constexpr double LN2_HI = 6.93147180369123816490e-01;
constexpr double LN2_LO = 1.90821492927058770002e-10;

constexpr double cexp(double x) {
    int n = (int)(x / 0.6931471805599453 + 0.5);
    double r = x - (double)n * LN2_HI - (double)n * LN2_LO;
    double s = 1.0;
    for (int k = 25; k >= 1; --k)
        s = 1.0 + r * s / (double)k;
    double scale = 1.0;
    for (int k = 0; k < n; ++k) scale *= 2.0;
    return s * scale;
}

struct Tables { float p[256]; float rp[256]; };

constexpr Tables make_tables() {
    Tables t{};
    for (int j = 0; j < 256; ++j) {
        double e = (double)j * (9.210340371976184 / 256.0); // j*ln(10000)/256
        double p = cexp(e);
        float pf = (j < NPAIR) ? (float)p : 1.0f;           // j=255 unused
        t.p[j]  = pf;
        t.rp[j] = (float)(1.0 / (double)pf);                // correctly rounded
    }
    return t;
}

__device__ const Tables g_tab = make_tables();

// sin/cos of a = fl(fi / p): Markstein 3-FMA correctly-rounded quotient,
// FMA Cody-Waite reduction (k <= 83444, residual < 1e-7), MUFU sin/cos,
// quadrant via magic-number mantissa bits.
__device__ __forceinline__ void sincos_ref(float fi, float p, float rp,
                                           float& sa, float& ca) {
    const float TWO_OVER_PI = 0.63661977236758134f;
    const float C1    = 1.57079637e+00f;    // fl(pi/2)
    const float C2    = -4.37113883e-08f;   // fl(pi/2 - C1)
    const float MAGIC = 12582912.0f;        // 1.5 * 2^23

    float a0 = fi * rp;
    float e  = fmaf(-p, a0, fi);
    float a  = fmaf(e, rp, a0);             // == div.rn(fi, p)

    float m  = fmaf(a, TWO_OVER_PI, MAGIC); // mantissa LSBs hold k (a >= 0)
    int   b  = __float_as_int(m);
    float kf = m - MAGIC;

    float r  = fmaf(-kf, C1, a);
    r        = fmaf(-kf, C2, r);

    float s, c;
    asm("sin.approx.f32 %0, %1;" : "=f"(s) : "f"(r));
    asm("cos.approx.f32 %0, %1;" : "=f"(c) : "f"(r));

    float ss = (b & 1) ? c : s;
    float cc = (b & 1) ? s : c;
    sa = __int_as_float(__float_as_int(ss) ^ ((b & 2) << 30));
    ca = __int_as_float(__float_as_int(cc) ^ (((b + 1) & 2) << 30));
}

__global__ __launch_bounds__(NTHREADS, 2) void emb_pe_kernel(
    const int* __restrict__ idx,
    const float* __restrict__ wl,
    float* __restrict__ out)
{
    extern __shared__ char smem_raw[];
    float4* __restrict__ s_wl  = reinterpret_cast<float4*>(smem_raw);
    int*    __restrict__ s_idx = reinterpret_cast<int*>(smem_raw + SMEM_WL_F4 * 16);

    const int tid   = threadIdx.x;
    const int lane  = tid & 31;
    const int w     = tid >> 5;               // warp id: row-within-group
    const int rg    = blockIdx.x;             // row group (0..255)
    const int strip = blockIdx.y;             // column strip (0..3)
    const int base  = rg * RPB;

    const float4* __restrict__ wl4 = reinterpret_cast<const float4*>(wl);

    // ---- phase 1: stage wordlist strip + idx chunk into SMEM ----
    #pragma unroll 1
    for (int c = tid; c < SMEM_WL_F4; c += NTHREADS) {
        const int v = c >> 5;                 // vocab row
        const int l = c & 31;                 // float4 within strip
        s_wl[c] = wl4[(size_t)v * (DEPTH / 4) + strip * STRIP_F4 + l];
    }
    s_idx[tid] = idx[base + tid];             // NTHREADS == RPB
    __syncthreads();

    // ---- per-thread PE constants ----
    const int j0 = strip * 64 + 2 * lane;     // this thread's sin column pair
    const int j1 = j0 + 1;
    const float p0 = g_tab.p[j0], rp0 = g_tab.rp[j0];
    const float p1 = g_tab.p[j1], rp1 = g_tab.rp[j1];
    const bool pe1 = (j1 < NPAIR);            // false only for strip 3, lane 31

    // ---- phase 2: 32 iterations x 16 rows (one row per warp) ----
    float4* __restrict__ op = reinterpret_cast<float4*>(out) +
                              (size_t)(base + w) * (DEPTH / 4) +
                              strip * STRIP_F4 + lane;
    float fi = (float)(base + w);             // exact, < 2^24

    #pragma unroll 2
    for (int it = 0; it < RPB / 16; ++it) {
        const int tok = s_idx[it * 16 + w];   // uniform in warp -> LDS broadcast
        float4 v = s_wl[tok * STRIP_F4 + lane];  // conflict-free LDS.128

        float s, c;
        sincos_ref(fi, p0, rp0, s, c); v.x += s; v.y += c;
        if (pe1) { sincos_ref(fi, p1, rp1, s, c); v.z += s; v.w += c; }

        __stcs(op, v);                        // streaming: output never re-read
        op += 16 * (DEPTH / 4);
        fi += 16.0f;
    }
}

extern "C" void kernel_launch(void* const* d_in, const int* in_sizes, int n_in,
                              void* d_out, int out_size) {
    const int*   idx = (const int*)d_in[0];
    const float* wl  = (const float*)d_in[1];
    float*       out = (float*)d_out;

    (void)in_sizes; (void)n_in; (void)out_size;

    cudaFuncSetAttribute(emb_pe_kernel,
                         cudaFuncAttributeMaxDynamicSharedMemorySize,
                         SMEM_BYTES);

    dim3 grid(ROWGROUPS, STRIPS);
    emb_pe_kernel<<<grid, NTHREADS, SMEM_BYTES>>>(idx, wl, out);
}

// round 10
// speedup vs baseline: 1.1956x; 1.1956x over previous
#include <cuda_runtime.h>

// Embedding_6940667150787: out[i][d] = wordlist[idx[i]][d] + PE(i, d)
// PE(i, 2j)   = sin(i / 10000^(j/256))   j in [0, 255)
// PE(i, 2j+1) = cos(i / 10000^(j/256))
// cols 510, 511: PE = 0 (emb only)

#define NROWS 131072
#define DEPTH 512
#define NPAIR 255
#define GRID  16384
#define ROWS_PER_BLOCK (NROWS / GRID)   // 8

// ---------------------------------------------------------------------------
// Compile-time double-precision exp: range reduction x = n*ln2 + r with a
// hi/lo split, then 25-term Taylor in |r| <= 0.3466. Accuracy ~1 ulp of
// double, far inside the fp32 rounding boundary after the final cast.
// ---------------------------------------------------------------------------
constexpr double LN2_HI = 6.93147180369123816490e-01;
constexpr double LN2_LO = 1.90821492927058770002e-10;

constexpr double cexp(double x) {
    int n = (int)(x / 0.6931471805599453 + 0.5);
    double r = x - (double)n * LN2_HI - (double)n * LN2_LO;
    double s = 1.0;
    for (int k = 25; k >= 1; --k)
        s = 1.0 + r * s / (double)k;
    double scale = 1.0;
    for (int k = 0; k < n; ++k) scale *= 2.0;
    return s * scale;
}

struct Tables { float p[256]; float rp[256]; };

constexpr Tables make_tables() {
    Tables t{};
    for (int j = 0; j < 256; ++j) {
        double e = (double)j * (9.210340371976184 / 256.0); // j*ln(10000)/256
        double p = cexp(e);
        float pf = (j < NPAIR) ? (float)p : 1.0f;           // j=255 unused
        t.p[j]  = pf;
        t.rp[j] = (float)(1.0 / (double)pf);                // correctly rounded
    }
    return t;
}

__device__ const Tables g_tab = make_tables();

// sin/cos of a = fl(fi / p), quotient correctly rounded (Markstein 3-FMA with
// correctly-rounded reciprocal), FMA Cody-Waite reduction (k <= 83444,
// residual < 1e-7), MUFU sin/cos, quadrant via magic-number mantissa bits.
__device__ __forceinline__ void sincos_ref(float fi, float p, float rp,
                                           float& sa, float& ca) {
    const float TWO_OVER_PI = 0.63661977236758134f;
    const float C1    = 1.57079637e+00f;    // fl(pi/2)
    const float C2    = -4.37113883e-08f;   // fl(pi/2 - C1)
    const float MAGIC = 12582912.0f;        // 1.5 * 2^23

    float a0 = fi * rp;
    float e  = fmaf(-p, a0, fi);
    float a  = fmaf(e, rp, a0);             // == div.rn(fi, p)

    // round-to-nearest via magic add: int quadrant + float k with no cvts
    float m  = fmaf(a, TWO_OVER_PI, MAGIC); // mantissa LSBs hold k (a >= 0)
    int   b  = __float_as_int(m);
    float kf = m - MAGIC;

    float r  = fmaf(-kf, C1, a);
    r        = fmaf(-kf, C2, r);

    float s, c;
    asm("sin.approx.f32 %0, %1;" : "=f"(s) : "f"(r));
    asm("cos.approx.f32 %0, %1;" : "=f"(c) : "f"(r));

    // quadrant fixup: swap when k odd, sign via bit XOR
    float ss = (b & 1) ? c : s;
    float cc = (b & 1) ? s : c;
    sa = __int_as_float(__float_as_int(ss) ^ ((b & 2) << 30));
    ca = __int_as_float(__float_as_int(cc) ^ (((b + 1) & 2) << 30));
}

__global__ __launch_bounds__(128, 16) void emb_pe_kernel(
    const int* __restrict__ idx,
    const float* __restrict__ wl,
    float* __restrict__ out)
{
    const int t  = threadIdx.x;          // thread t owns cols 4t..4t+3
    const int j0 = 2 * t;
    const int j1 = 2 * t + 1;

    const float p0 = g_tab.p[j0], rp0 = g_tab.rp[j0];
    const float p1 = g_tab.p[j1], rp1 = g_tab.rp[j1];
    const bool pe1 = (j1 < NPAIR);       // false only for t == 127 (cols 510,511)

    const int base = blockIdx.x * ROWS_PER_BLOCK;
    const float4* __restrict__ wl4 = reinterpret_cast<const float4*>(wl);

    // running pointers: no per-iteration index IMAD chains
    const int2* __restrict__ ip = reinterpret_cast<const int2*>(idx + base);
    float4* __restrict__     op = reinterpret_cast<float4*>(out) +
                                  (size_t)base * (DEPTH / 4) + t;

    float fi = (float)base;              // exact, base < 2^24

    #pragma unroll 1
    for (int k = 0; k < ROWS_PER_BLOCK; k += 2) {
        // one 8B load for both row indices (base is even -> 8B aligned)
        const int2 tok = *ip++;

        // two independent gather chains in flight
        float4 w0 = __ldg(wl4 + (size_t)tok.x * (DEPTH / 4) + t);
        float4 w1 = __ldg(wl4 + (size_t)tok.y * (DEPTH / 4) + t);

        float s, c;
        const float f0 = fi;
        const float f1 = fi + 1.0f;      // exact small-int add

        sincos_ref(f0, p0, rp0, s, c); w0.x += s; w0.y += c;
        if (pe1) { sincos_ref(f0, p1, rp1, s, c); w0.z += s; w0.w += c; }

        sincos_ref(f1, p0, rp0, s, c); w1.x += s; w1.y += c;
        if (pe1) { sincos_ref(f1, p1, rp1, s, c); w1.z += s; w1.w += c; }

        // streaming stores: output never re-read; keep L2 for the wordlist
        __stcs(op, w0);
        __stcs(op + (DEPTH / 4), w1);
        op += 2 * (DEPTH / 4);

        fi += 2.0f;
    }
}

extern "C" void kernel_launch(void* const* d_in, const int* in_sizes, int n_in,
                              void* d_out, int out_size) {
    const int*   idx = (const int*)d_in[0];
    const float* wl  = (const float*)d_in[1];
    float*       out = (float*)d_out;

    (void)in_sizes; (void)n_in; (void)out_size;

    emb_pe_kernel<<<GRID, 128>>>(idx, wl, out);
}